// round 7
// baseline (speedup 1.0000x reference)
#include <cuda_runtime.h>
#include <math.h>

#define BS 32
#define NF 33
#define KDIM 4096
#define SATN (32*64*64*64)
#define NKC 16           // k-chunks per freq in fgemm

typedef unsigned long long ull;

// -------- device scratch --------
__device__ float2 g_Sh[(size_t)NF * BS * KDIM];
__device__ float2 g_Gh[(size_t)NF * BS * KDIM];
__device__ float2 g_Sw[(size_t)NF * BS * KDIM];
__device__ float2 g_Gw[(size_t)NF * BS * KDIM];
__device__ float2 g_CpH[NKC * NF * BS * BS];
__device__ float2 g_CpW[NKC * NF * BS * BS];
__device__ float2 g_tw[NF * 64];
__device__ float  g_normp[2048];

// -------- twiddle init: g_tw[f*64+n] = (cos,sin)(2*pi*f*n/64) --------
__global__ void k_init() {
    int idx = blockIdx.x * blockDim.x + threadIdx.x;
    if (idx < NF * 64) {
        int f = idx >> 6, n = idx & 63;
        float x = (float)((f * n) & 63) / 32.0f;
        float s, c;
        sincospif(x, &s, &c);
        g_tw[idx] = make_float2(c, s);
    }
}

// packed f32x2 fma: acc(2 lanes) += a(2 lanes) * b(2 lanes)
__device__ __forceinline__ void fma2(ull& acc, ull a, ull b) {
    asm("fma.rn.f32x2 %0, %1, %2, %0;" : "+l"(acc) : "l"(a), "l"(b));
}
__device__ __forceinline__ ull pk2(float x) {          // splat x into both lanes
    unsigned u = __float_as_uint(x);
    return ((ull)u << 32) | u;
}
__device__ __forceinline__ float f2lo(ull p) { return __uint_as_float((unsigned)p); }
__device__ __forceinline__ float f2hi(ull p) { return __uint_as_float((unsigned)(p >> 32)); }

// -------- DFT helpers (R6-proven, unchanged) --------
__device__ __forceinline__ void dft_build(
    const float* slab, float* se, float* so, int axisH, int cc, int col, int m)
{
#pragma unroll
    for (int nn = 0; nn < 8; nn++) {
        int n = m + 4 * nn;
        float a, bb;
        if (axisH) {
            a  = slab[n * 65 + cc];
            bb = n ? slab[(64 - n) * 65 + cc] : 0.f;
        } else {
            a  = slab[cc * 65 + n];
            bb = n ? slab[cc * 65 + (64 - n)] : 0.f;
        }
        se[n * 65 + col] = a + bb;
        so[n * 65 + col] = a - bb;
    }
    if (m == 0)
        se[32 * 65 + col] = axisH ? slab[32 * 65 + cc] : slab[cc * 65 + 32];
}

__device__ __forceinline__ void dft_compute(
    const float* se, const float* so, const float2* stw,
    float2* __restrict__ dst, int i, size_t off, int col, int m)
{
    float e0  = se[col];
    float e32 = se[32 * 65 + col];
    float sgn = (m & 1) ? -1.f : 1.f;
    float base = fmaf(sgn, e32, e0);

#pragma unroll
    for (int u = 0; u < 4; u++) {
        int f1 = m + 4 * u;
        const float2* t1 = stw + f1 * 64;
        float ar1 = base, ar2 = base, ai1 = 0.f, ai2 = 0.f;
#pragma unroll
        for (int n = 1; n < 32; n++) {
            float en = se[n * 65 + col];
            float on = so[n * 65 + col];
            float2 w = t1[n];
            ar1 = fmaf(en, w.x, ar1);
            ai1 = fmaf(on, w.y, ai1);
            float c2, s2;
            if ((n & 3) == 0)      { c2 =  w.x; s2 =  w.y; }
            else if ((n & 3) == 1) { c2 = -w.y; s2 =  w.x; }
            else if ((n & 3) == 2) { c2 = -w.x; s2 = -w.y; }
            else                   { c2 =  w.y; s2 = -w.x; }
            ar2 = fmaf(en, c2, ar2);
            ai2 = fmaf(on, s2, ai2);
        }
        dst[((size_t)f1 * BS + i) * KDIM + off]        = make_float2(ar1, -ai1);
        dst[((size_t)(f1 + 16) * BS + i) * KDIM + off] = make_float2(ar2, -ai2);
    }
    if (m == 0) {
        float ar = e0 + e32;
        float sg = -1.f;
#pragma unroll
        for (int n = 1; n < 32; n++) {
            ar = fmaf(se[n * 65 + col], sg, ar);
            sg = -sg;
        }
        dst[((size_t)32 * BS + i) * KDIM + off] = make_float2(ar, 0.f);
    }
}

// -------- merged DFT: sat+grd, H+W axes, passthrough copy, norm partials --------
__global__ void __launch_bounds__(256, 4)
k_dft3(const float* __restrict__ sat, const float* __restrict__ grd,
       float* __restrict__ out)
{
    __shared__ float slab[64 * 65];
    __shared__ __align__(16) float2 stw[16 * 64];
    __shared__ float se[33 * 65];
    __shared__ float so[32 * 65];
    __shared__ float red[8];

    int b = blockIdx.x;
    int tid = threadIdx.x;
    int is_grd = (b >= 2048);
    int b2 = is_grd ? (b - 2048) : b;
    const float* p = (is_grd ? grd : sat) + (size_t)b2 * 4096;
    float* op = out + (is_grd ? (size_t)SATN : 0) + (size_t)b2 * 4096;

    float nacc = 0.f;
#pragma unroll
    for (int t = 0; t < 16; t++) {
        int idx = tid + t * 256;
        float v = p[idx];
        slab[(idx >> 6) * 65 + (idx & 63)] = v;
        op[idx] = v;
        nacc = fmaf(v, v, nacc);
    }
    for (int t = tid; t < 16 * 64; t += 256) stw[t] = g_tw[t];

    if (!is_grd) {
#pragma unroll
        for (int o = 16; o > 0; o >>= 1)
            nacc += __shfl_down_sync(0xffffffffu, nacc, o);
        if ((tid & 31) == 0) red[tid >> 5] = nacc;
    }
    __syncthreads();
    if (!is_grd && tid == 0) {
        float s = 0.f;
#pragma unroll
        for (int w = 0; w < 8; w++) s += red[w];
        g_normp[b2] = s;
    }

    int col = tid & 63;
    int m   = tid >> 6;
    int i = b2 >> 6, c = b2 & 63;
    size_t off = (size_t)c * 64 + col;

    {
        int cc = is_grd ? (63 - col) : col;
        dft_build(slab, se, so, 1, cc, col, m);
        __syncthreads();
        dft_compute(se, so, stw, is_grd ? g_Gh : g_Sh, i, off, col, m);
    }
    __syncthreads();
    {
        dft_build(slab, se, so, 0, col, col, m);
        __syncthreads();
        dft_compute(se, so, stw, is_grd ? g_Gw : g_Sw, i, off, col, m);
    }
}

// -------- per-frequency complex GEMM, f32x2 packed inner loop --------
// grid = 2 * 33 * 16 = 1056 blocks, 256 threads, 4 blocks/SM.
// sS: float2 [k][i] pad-34. sGp: ulonglong2 [k][j] pad-33, element = (splat(re), splat(im)).
// Per complex MAC a*conj(b): P1 += (a.re,a.im)*splat(b.re); P2 += (a.re,a.im)*splat(b.im);
// final re = P1.lo + P2.hi, im = P1.hi - P2.lo. Exact same products as the scalar form.
__global__ void __launch_bounds__(256, 4) k_fgemm3() {
    __shared__ __align__(16) float2     sS[64 * 34];
    __shared__ __align__(16) ulonglong2 sGp[64 * 33];

    int bid = blockIdx.x;
    int sel = (bid >= NF * NKC);
    if (sel) bid -= NF * NKC;
    int f  = bid >> 4;
    int kc = bid & 15;

    const float2* S = sel ? g_Sw : g_Sh;
    const float2* G = sel ? g_Gw : g_Gh;
    float2* Cp      = sel ? g_CpW : g_CpH;

    int tid = threadIdx.x;
    int i0 = (tid >> 4) * 2;
    int j0 = (tid & 15) * 2;
    int li = tid >> 3;
    int ls = tid & 7;

    const float2* Sb = S + (size_t)f * BS * KDIM + kc * 256;
    const float2* Gb = G + (size_t)f * BS * KDIM + kc * 256;
    const float4* Sg4 = (const float4*)(Sb + (size_t)li * KDIM);
    const float4* Gg4 = (const float4*)(Gb + (size_t)li * KDIM);

    ull P1_00 = 0, P2_00 = 0, P1_01 = 0, P2_01 = 0;
    ull P1_10 = 0, P2_10 = 0, P1_11 = 0, P2_11 = 0;

    const ulonglong2* sSu = (const ulonglong2*)sS;
    int ia = i0 >> 1;

    for (int kt = 0; kt < 4; kt++) {          // 4 tiles of 64 k
        __syncthreads();
#pragma unroll
        for (int u = 0; u < 4; u++) {
            int k4 = ls + u * 8;              // complex k = 2*k4, 2*k4+1 for row li
            float4 s = Sg4[kt * 32 + k4];
            float4 g = Gg4[kt * 32 + k4];
            sS[(2 * k4)     * 34 + li] = make_float2(s.x, s.y);
            sS[(2 * k4 + 1) * 34 + li] = make_float2(s.z, s.w);
            sGp[(2 * k4)     * 33 + li] = make_ulonglong2(pk2(g.x), pk2(g.y));
            sGp[(2 * k4 + 1) * 33 + li] = make_ulonglong2(pk2(g.z), pk2(g.w));
        }
        __syncthreads();
#pragma unroll 16
        for (int k = 0; k < 64; k++) {
            ulonglong2 av  = sSu[k * 17 + ia];       // (a_i0, a_i0+1) packed complex
            ulonglong2 bv0 = sGp[k * 33 + j0];       // (splat re, splat im) for j0
            ulonglong2 bv1 = sGp[k * 33 + j0 + 1];   // for j0+1
            fma2(P1_00, av.x, bv0.x);  fma2(P2_00, av.x, bv0.y);
            fma2(P1_01, av.x, bv1.x);  fma2(P2_01, av.x, bv1.y);
            fma2(P1_10, av.y, bv0.x);  fma2(P2_10, av.y, bv0.y);
            fma2(P1_11, av.y, bv1.x);  fma2(P2_11, av.y, bv1.y);
        }
    }
    float2* outp = Cp + ((size_t)kc * NF + f) * BS * BS;
    outp[i0 * 32 + j0]           = make_float2(f2lo(P1_00) + f2hi(P2_00), f2hi(P1_00) - f2lo(P2_00));
    outp[i0 * 32 + j0 + 1]       = make_float2(f2lo(P1_01) + f2hi(P2_01), f2hi(P1_01) - f2lo(P2_01));
    outp[(i0 + 1) * 32 + j0]     = make_float2(f2lo(P1_10) + f2hi(P2_10), f2hi(P1_10) - f2lo(P2_10));
    outp[(i0 + 1) * 32 + j0 + 1] = make_float2(f2lo(P1_11) + f2hi(P2_11), f2hi(P1_11) - f2lo(P2_11));
}

// -------- fused inverse transform + norm + first-max argmax + distance --------
// grid = 1024 blocks (i*32+j), 64 threads (one per shift)
__global__ void k_inv(float* __restrict__ out_dist, float* __restrict__ out_orien_f) {
    __shared__ float2 CH[NF], CW[NF];
    __shared__ float valsH[64], valsW[64];
    __shared__ float nred[2];
    int i = blockIdx.x >> 5, j = blockIdx.x & 31;
    int s = threadIdx.x;

    // norm[i] reduction (redundant per block; deterministic tree)
    float nv = g_normp[i * 64 + s];
#pragma unroll
    for (int o = 16; o > 0; o >>= 1) nv += __shfl_down_sync(0xffffffffu, nv, o);
    if ((s & 31) == 0) nred[s >> 5] = nv;

    if (s < NF) {
        float xr = 0, xi = 0, yr = 0, yi = 0;
#pragma unroll
        for (int kc = 0; kc < NKC; kc++) {
            float2 a = g_CpH[((kc * NF + s) * BS + i) * BS + j];
            float2 b = g_CpW[((kc * NF + s) * BS + i) * BS + j];
            xr += a.x; xi += a.y; yr += b.x; yi += b.y;
        }
        CH[s] = make_float2(xr, xi);
        CW[s] = make_float2(yr, yi);
    }
    __syncthreads();

    float sgn = (s & 1) ? -1.f : 1.f;
    float accH = CH[0].x + sgn * CH[32].x;
    float accW = CW[0].x + sgn * CW[32].x;
#pragma unroll
    for (int f = 1; f < 32; f++) {
        float2 t = g_tw[f * 64 + s];
        accH += 2.f * (CH[f].x * t.x - CH[f].y * t.y);
        accW += 2.f * (CW[f].x * t.x - CW[f].y * t.y);
    }
    valsH[s] = accH;
    valsW[s] = accW;
    __syncthreads();

    if (s == 0) {
        float best = valsH[0]; int bi = 0;
        for (int t = 1; t < 64; t++)
            if (valsH[t] > best) { best = valsH[t]; bi = t; }   // first max
        out_orien_f[i * 32 + j] = (float)bi;
        float nrm = sqrtf(nred[0] + nred[1] + 1e-8f);
        float q = valsW[bi] * (1.f / 64.f);
        float dot = q / nrm;
        out_dist[j * 32 + i] = 2.f - 2.f * dot;
    }
}

extern "C" void kernel_launch(void* const* d_in, const int* in_sizes, int n_in,
                              void* d_out, int out_size) {
    (void)in_sizes; (void)n_in; (void)out_size;
    const float* sat = (const float*)d_in[0];
    const float* grd = (const float*)d_in[1];
    float* out = (float*)d_out;

    k_init<<<9, 256>>>();

    k_dft3<<<4096, 256>>>(sat, grd, out);

    k_fgemm3<<<2 * NF * NKC, 256>>>();

    float* out_dist  = out + (size_t)2 * SATN;
    float* out_orien = out + (size_t)2 * SATN + 1024;
    k_inv<<<1024, 64>>>(out_dist, out_orien);
}

// round 8
// speedup vs baseline: 1.3435x; 1.3435x over previous
#include <cuda_runtime.h>
#include <math.h>

#define BS 32
#define NF 33
#define KDIM 4096
#define SATN (32*64*64*64)
#define NKC 8            // k-chunks per freq in fgemm

// -------- device scratch --------
__device__ float2 g_Sh[(size_t)NF * BS * KDIM];
__device__ float2 g_Gh[(size_t)NF * BS * KDIM];
__device__ float2 g_Sw[(size_t)NF * BS * KDIM];
__device__ float2 g_Gw[(size_t)NF * BS * KDIM];
__device__ float2 g_CpH[NKC * NF * BS * BS];
__device__ float2 g_CpW[NKC * NF * BS * BS];
__device__ float2 g_tw[NF * 64];
__device__ float  g_normp[2048];

// -------- twiddle init: g_tw[f*64+n] = (cos,sin)(2*pi*f*n/64) --------
__global__ void k_init() {
    int idx = blockIdx.x * blockDim.x + threadIdx.x;
    if (idx < NF * 64) {
        int f = idx >> 6, n = idx & 63;
        float x = (float)((f * n) & 63) / 32.0f;
        float s, c;
        sincospif(x, &s, &c);
        g_tw[idx] = make_float2(c, s);
    }
}

// -------- DFT helpers (R6-proven, unchanged) --------
__device__ __forceinline__ void dft_build(
    const float* slab, float* se, float* so, int axisH, int cc, int col, int m)
{
#pragma unroll
    for (int nn = 0; nn < 8; nn++) {
        int n = m + 4 * nn;
        float a, bb;
        if (axisH) {
            a  = slab[n * 65 + cc];
            bb = n ? slab[(64 - n) * 65 + cc] : 0.f;
        } else {
            a  = slab[cc * 65 + n];
            bb = n ? slab[cc * 65 + (64 - n)] : 0.f;
        }
        se[n * 65 + col] = a + bb;
        so[n * 65 + col] = a - bb;
    }
    if (m == 0)
        se[32 * 65 + col] = axisH ? slab[32 * 65 + cc] : slab[cc * 65 + 32];
}

__device__ __forceinline__ void dft_compute(
    const float* se, const float* so, const float2* stw,
    float2* __restrict__ dst, int i, size_t off, int col, int m)
{
    float e0  = se[col];
    float e32 = se[32 * 65 + col];
    float sgn = (m & 1) ? -1.f : 1.f;
    float base = fmaf(sgn, e32, e0);

#pragma unroll
    for (int u = 0; u < 4; u++) {
        int f1 = m + 4 * u;
        const float2* t1 = stw + f1 * 64;
        float ar1 = base, ar2 = base, ai1 = 0.f, ai2 = 0.f;
#pragma unroll
        for (int n = 1; n < 32; n++) {
            float en = se[n * 65 + col];
            float on = so[n * 65 + col];
            float2 w = t1[n];
            ar1 = fmaf(en, w.x, ar1);
            ai1 = fmaf(on, w.y, ai1);
            float c2, s2;
            if ((n & 3) == 0)      { c2 =  w.x; s2 =  w.y; }
            else if ((n & 3) == 1) { c2 = -w.y; s2 =  w.x; }
            else if ((n & 3) == 2) { c2 = -w.x; s2 = -w.y; }
            else                   { c2 =  w.y; s2 = -w.x; }
            ar2 = fmaf(en, c2, ar2);
            ai2 = fmaf(on, s2, ai2);
        }
        dst[((size_t)f1 * BS + i) * KDIM + off]        = make_float2(ar1, -ai1);
        dst[((size_t)(f1 + 16) * BS + i) * KDIM + off] = make_float2(ar2, -ai2);
    }
    if (m == 0) {
        float ar = e0 + e32;
        float sg = -1.f;
#pragma unroll
        for (int n = 1; n < 32; n++) {
            ar = fmaf(se[n * 65 + col], sg, ar);
            sg = -sg;
        }
        dst[((size_t)32 * BS + i) * KDIM + off] = make_float2(ar, 0.f);
    }
}

// -------- merged DFT: sat+grd, H+W axes, passthrough copy, norm partials --------
__global__ void __launch_bounds__(256, 4)
k_dft3(const float* __restrict__ sat, const float* __restrict__ grd,
       float* __restrict__ out)
{
    __shared__ float slab[64 * 65];
    __shared__ __align__(16) float2 stw[16 * 64];
    __shared__ float se[33 * 65];
    __shared__ float so[32 * 65];
    __shared__ float red[8];

    int b = blockIdx.x;
    int tid = threadIdx.x;
    int is_grd = (b >= 2048);
    int b2 = is_grd ? (b - 2048) : b;
    const float* p = (is_grd ? grd : sat) + (size_t)b2 * 4096;
    float* op = out + (is_grd ? (size_t)SATN : 0) + (size_t)b2 * 4096;

    float nacc = 0.f;
#pragma unroll
    for (int t = 0; t < 16; t++) {
        int idx = tid + t * 256;
        float v = p[idx];
        slab[(idx >> 6) * 65 + (idx & 63)] = v;
        op[idx] = v;
        nacc = fmaf(v, v, nacc);
    }
    for (int t = tid; t < 16 * 64; t += 256) stw[t] = g_tw[t];

    if (!is_grd) {
#pragma unroll
        for (int o = 16; o > 0; o >>= 1)
            nacc += __shfl_down_sync(0xffffffffu, nacc, o);
        if ((tid & 31) == 0) red[tid >> 5] = nacc;
    }
    __syncthreads();
    if (!is_grd && tid == 0) {
        float s = 0.f;
#pragma unroll
        for (int w = 0; w < 8; w++) s += red[w];
        g_normp[b2] = s;
    }

    int col = tid & 63;
    int m   = tid >> 6;
    int i = b2 >> 6, c = b2 & 63;
    size_t off = (size_t)c * 64 + col;

    {
        int cc = is_grd ? (63 - col) : col;
        dft_build(slab, se, so, 1, cc, col, m);
        __syncthreads();
        dft_compute(se, so, stw, is_grd ? g_Gh : g_Sh, i, off, col, m);
    }
    __syncthreads();
    {
        dft_build(slab, se, so, 0, col, col, m);
        __syncthreads();
        dft_compute(se, so, stw, is_grd ? g_Gw : g_Sw, i, off, col, m);
    }
}

// -------- per-frequency complex GEMM: C[f][i][j] = sum_k S[f][i][k]*conj(G[f][j][k]) --------
// R6-proven scalar inner loop; k-tile halved 64->32 (smem 17.4KB) for 4 blocks/SM.
__global__ void __launch_bounds__(256, 4) k_fgemm2() {
    __shared__ __align__(16) float2 sS[32 * 34];
    __shared__ __align__(16) float2 sG[32 * 34];

    int bid = blockIdx.x;
    int sel = (bid >= NF * NKC);
    if (sel) bid -= NF * NKC;
    int f  = bid >> 3;
    int kc = bid & 7;

    const float2* S = sel ? g_Sw : g_Sh;
    const float2* G = sel ? g_Gw : g_Gh;
    float2* Cp      = sel ? g_CpW : g_CpH;

    int tid = threadIdx.x;
    int i0 = (tid >> 4) * 2;
    int j0 = (tid & 15) * 2;
    int li = tid >> 3;
    int ls = tid & 7;

    const float2* Sb = S + (size_t)f * BS * KDIM + kc * 512;
    const float2* Gb = G + (size_t)f * BS * KDIM + kc * 512;
    const float4* Sg4 = (const float4*)(Sb + (size_t)li * KDIM);
    const float4* Gg4 = (const float4*)(Gb + (size_t)li * KDIM);

    float c00r = 0, c00i = 0, c01r = 0, c01i = 0;
    float c10r = 0, c10i = 0, c11r = 0, c11i = 0;

    const float4* sS4 = (const float4*)sS;
    const float4* sG4 = (const float4*)sG;
    int ia = i0 >> 1;
    int jb = j0 >> 1;

    for (int kt = 0; kt < 16; kt++) {          // 16 tiles of 32 k
        __syncthreads();
#pragma unroll
        for (int u = 0; u < 2; u++) {
            int k4 = ls + u * 8;               // float4 index 0..15 -> complex k 0..31
            float4 s = Sg4[kt * 16 + k4];
            float4 g = Gg4[kt * 16 + k4];
            sS[(2 * k4)     * 34 + li] = make_float2(s.x, s.y);
            sS[(2 * k4 + 1) * 34 + li] = make_float2(s.z, s.w);
            sG[(2 * k4)     * 34 + li] = make_float2(g.x, g.y);
            sG[(2 * k4 + 1) * 34 + li] = make_float2(g.z, g.w);
        }
        __syncthreads();
#pragma unroll 16
        for (int k = 0; k < 32; k++) {
            float4 a = sS4[k * 17 + ia];
            float4 b = sG4[k * 17 + jb];
            c00r += a.x * b.x + a.y * b.y;  c00i += a.y * b.x - a.x * b.y;
            c01r += a.x * b.z + a.y * b.w;  c01i += a.y * b.z - a.x * b.w;
            c10r += a.z * b.x + a.w * b.y;  c10i += a.w * b.x - a.z * b.y;
            c11r += a.z * b.z + a.w * b.w;  c11i += a.w * b.z - a.z * b.w;
        }
    }
    float2* outp = Cp + ((size_t)kc * NF + f) * BS * BS;
    outp[i0 * 32 + j0]           = make_float2(c00r, c00i);
    outp[i0 * 32 + j0 + 1]       = make_float2(c01r, c01i);
    outp[(i0 + 1) * 32 + j0]     = make_float2(c10r, c10i);
    outp[(i0 + 1) * 32 + j0 + 1] = make_float2(c11r, c11i);
}

// -------- fused inverse transform + norm + first-max argmax + distance --------
__global__ void k_inv(float* __restrict__ out_dist, float* __restrict__ out_orien_f) {
    __shared__ float2 CH[NF], CW[NF];
    __shared__ float valsH[64], valsW[64];
    __shared__ float nred[2];
    int i = blockIdx.x >> 5, j = blockIdx.x & 31;
    int s = threadIdx.x;

    // norm[i] reduction (redundant per block; deterministic tree)
    float nv = g_normp[i * 64 + s];
#pragma unroll
    for (int o = 16; o > 0; o >>= 1) nv += __shfl_down_sync(0xffffffffu, nv, o);
    if ((s & 31) == 0) nred[s >> 5] = nv;

    if (s < NF) {
        float xr = 0, xi = 0, yr = 0, yi = 0;
#pragma unroll
        for (int kc = 0; kc < NKC; kc++) {
            float2 a = g_CpH[((kc * NF + s) * BS + i) * BS + j];
            float2 b = g_CpW[((kc * NF + s) * BS + i) * BS + j];
            xr += a.x; xi += a.y; yr += b.x; yi += b.y;
        }
        CH[s] = make_float2(xr, xi);
        CW[s] = make_float2(yr, yi);
    }
    __syncthreads();

    float sgn = (s & 1) ? -1.f : 1.f;
    float accH = CH[0].x + sgn * CH[32].x;
    float accW = CW[0].x + sgn * CW[32].x;
#pragma unroll
    for (int f = 1; f < 32; f++) {
        float2 t = g_tw[f * 64 + s];
        accH += 2.f * (CH[f].x * t.x - CH[f].y * t.y);
        accW += 2.f * (CW[f].x * t.x - CW[f].y * t.y);
    }
    valsH[s] = accH;
    valsW[s] = accW;
    __syncthreads();

    if (s == 0) {
        float best = valsH[0]; int bi = 0;
        for (int t = 1; t < 64; t++)
            if (valsH[t] > best) { best = valsH[t]; bi = t; }   // first max
        out_orien_f[i * 32 + j] = (float)bi;
        float nrm = sqrtf(nred[0] + nred[1] + 1e-8f);
        float q = valsW[bi] * (1.f / 64.f);
        float dot = q / nrm;
        out_dist[j * 32 + i] = 2.f - 2.f * dot;
    }
}

extern "C" void kernel_launch(void* const* d_in, const int* in_sizes, int n_in,
                              void* d_out, int out_size) {
    (void)in_sizes; (void)n_in; (void)out_size;
    const float* sat = (const float*)d_in[0];
    const float* grd = (const float*)d_in[1];
    float* out = (float*)d_out;

    k_init<<<9, 256>>>();

    k_dft3<<<4096, 256>>>(sat, grd, out);

    k_fgemm2<<<2 * NF * NKC, 256>>>();

    float* out_dist  = out + (size_t)2 * SATN;
    float* out_orien = out + (size_t)2 * SATN + 1024;
    k_inv<<<1024, 64>>>(out_dist, out_orien);
}

// round 9
// speedup vs baseline: 1.5397x; 1.1460x over previous
#include <cuda_runtime.h>
#include <math.h>

#define BS 32
#define NF 33
#define KDIM 4096
#define SATN (32*64*64*64)
#define NKC 8            // k-chunk blocks per freq in fgemm
#define NKC2 16          // Cp partial slots (NKC * 2 k-subsets)

// -------- device scratch --------
__device__ float2 g_Sh[(size_t)NF * BS * KDIM];
__device__ float2 g_Gh[(size_t)NF * BS * KDIM];
__device__ float2 g_Sw[(size_t)NF * BS * KDIM];
__device__ float2 g_Gw[(size_t)NF * BS * KDIM];
__device__ float2 g_CpH[NKC2 * NF * BS * BS];
__device__ float2 g_CpW[NKC2 * NF * BS * BS];
__device__ float2 g_tw[NF * 64];
__device__ float  g_normp[2048];

// -------- twiddle init: g_tw[f*64+n] = (cos,sin)(2*pi*f*n/64) --------
__global__ void k_init() {
    int idx = blockIdx.x * blockDim.x + threadIdx.x;
    if (idx < NF * 64) {
        int f = idx >> 6, n = idx & 63;
        float x = (float)((f * n) & 63) / 32.0f;
        float s, c;
        sincospif(x, &s, &c);
        g_tw[idx] = make_float2(c, s);
    }
}

// -------- DFT helpers --------
__device__ __forceinline__ void dft_build(
    const float* slab, float* se, float* so, int axisH, int cc, int col, int m)
{
#pragma unroll
    for (int nn = 0; nn < 8; nn++) {
        int n = m + 4 * nn;
        float a, bb;
        if (axisH) {
            a  = slab[n * 65 + cc];
            bb = n ? slab[(64 - n) * 65 + cc] : 0.f;
        } else {
            a  = slab[cc * 65 + n];
            bb = n ? slab[cc * 65 + (64 - n)] : 0.f;
        }
        se[n * 65 + col] = a + bb;
        so[n * 65 + col] = a - bb;
    }
    if (m == 0)
        se[32 * 65 + col] = axisH ? slab[32 * 65 + cc] : slab[cc * 65 + 32];
}

// Inverted loops: n outer (en/on loaded ONCE per n), u inner.
// Per-accumulator math and summation order identical to the R6/R8-proven version.
__device__ __forceinline__ void dft_compute(
    const float* se, const float* so, const float2* stw,
    float2* __restrict__ dst, int i, size_t off, int col, int m)
{
    float e0  = se[col];
    float e32 = se[32 * 65 + col];
    float sgn = (m & 1) ? -1.f : 1.f;
    float base = fmaf(sgn, e32, e0);

    float ar1[4], ai1[4], ar2[4], ai2[4];
#pragma unroll
    for (int u = 0; u < 4; u++) { ar1[u] = base; ar2[u] = base; ai1[u] = 0.f; ai2[u] = 0.f; }

#pragma unroll
    for (int n = 1; n < 32; n++) {
        float en = se[n * 65 + col];
        float on = so[n * 65 + col];
#pragma unroll
        for (int u = 0; u < 4; u++) {
            float2 w = stw[(m + 4 * u) * 64 + n];
            ar1[u] = fmaf(en, w.x, ar1[u]);
            ai1[u] = fmaf(on, w.y, ai1[u]);
            float c2, s2;                      // twiddle(f1+16, n) = (-i)^n rotation, exact
            if ((n & 3) == 0)      { c2 =  w.x; s2 =  w.y; }
            else if ((n & 3) == 1) { c2 = -w.y; s2 =  w.x; }
            else if ((n & 3) == 2) { c2 = -w.x; s2 = -w.y; }
            else                   { c2 =  w.y; s2 = -w.x; }
            ar2[u] = fmaf(en, c2, ar2[u]);
            ai2[u] = fmaf(on, s2, ai2[u]);
        }
    }
#pragma unroll
    for (int u = 0; u < 4; u++) {
        int f1 = m + 4 * u;
        dst[((size_t)f1 * BS + i) * KDIM + off]        = make_float2(ar1[u], -ai1[u]);
        dst[((size_t)(f1 + 16) * BS + i) * KDIM + off] = make_float2(ar2[u], -ai2[u]);
    }
    if (m == 0) {                              // f = 32: cos = (-1)^n, sin = 0
        float ar = e0 + e32;
        float sg = -1.f;
#pragma unroll
        for (int n = 1; n < 32; n++) {
            ar = fmaf(se[n * 65 + col], sg, ar);
            sg = -sg;
        }
        dst[((size_t)32 * BS + i) * KDIM + off] = make_float2(ar, 0.f);
    }
}

// -------- merged DFT: sat+grd, H+W axes, passthrough copy, norm partials --------
__global__ void __launch_bounds__(256, 4)
k_dft3(const float* __restrict__ sat, const float* __restrict__ grd,
       float* __restrict__ out)
{
    __shared__ float slab[64 * 65];
    __shared__ __align__(16) float2 stw[16 * 64];
    __shared__ float se[33 * 65];
    __shared__ float so[32 * 65];
    __shared__ float red[8];

    int b = blockIdx.x;
    int tid = threadIdx.x;
    int is_grd = (b >= 2048);
    int b2 = is_grd ? (b - 2048) : b;
    const float* p = (is_grd ? grd : sat) + (size_t)b2 * 4096;
    float* op = out + (is_grd ? (size_t)SATN : 0) + (size_t)b2 * 4096;

    float nacc = 0.f;
#pragma unroll
    for (int t = 0; t < 16; t++) {
        int idx = tid + t * 256;
        float v = p[idx];
        slab[(idx >> 6) * 65 + (idx & 63)] = v;
        op[idx] = v;
        nacc = fmaf(v, v, nacc);
    }
    for (int t = tid; t < 16 * 64; t += 256) stw[t] = g_tw[t];

    if (!is_grd) {
#pragma unroll
        for (int o = 16; o > 0; o >>= 1)
            nacc += __shfl_down_sync(0xffffffffu, nacc, o);
        if ((tid & 31) == 0) red[tid >> 5] = nacc;
    }
    __syncthreads();
    if (!is_grd && tid == 0) {
        float s = 0.f;
#pragma unroll
        for (int w = 0; w < 8; w++) s += red[w];
        g_normp[b2] = s;
    }

    int col = tid & 63;
    int m   = tid >> 6;
    int i = b2 >> 6, c = b2 & 63;
    size_t off = (size_t)c * 64 + col;

    {
        int cc = is_grd ? (63 - col) : col;
        dft_build(slab, se, so, 1, cc, col, m);
        __syncthreads();
        dft_compute(se, so, stw, is_grd ? g_Gh : g_Sh, i, off, col, m);
    }
    __syncthreads();
    {
        dft_build(slab, se, so, 0, col, col, m);
        __syncthreads();
        dft_compute(se, so, stw, is_grd ? g_Gw : g_Sw, i, off, col, m);
    }
}

// -------- per-frequency complex GEMM: C[f][i][j] = sum_k S[f][i][k]*conj(G[f][j][k]) --------
// 2x4 complex tiles: 128 tile-threads (16 i-tiles x 8 j-tiles) x 2 k-subsets.
// Per k: 12B/FFMA-lane... (32 FFMA per 48 bytes) -> LDS floor below the FMA floor.
// Staging identical to R8 (proven).
__global__ void __launch_bounds__(256, 4) k_fgemm2() {
    __shared__ __align__(16) float2 sS[32 * 34];
    __shared__ __align__(16) float2 sG[32 * 34];

    int bid = blockIdx.x;
    int sel = (bid >= NF * NKC);
    if (sel) bid -= NF * NKC;
    int f  = bid >> 3;
    int kc = bid & 7;

    const float2* S = sel ? g_Sw : g_Sh;
    const float2* G = sel ? g_Gw : g_Gh;
    float2* Cp      = sel ? g_CpW : g_CpH;

    int tid = threadIdx.x;
    int li = tid >> 3;                 // staging row 0..31
    int ls = tid & 7;                  // staging float4 k-index base
    int t    = tid & 127;              // tile-thread
    int ksub = tid >> 7;               // 0..1 -> k-subrange within staged tile
    int i0 = ((t >> 3) & 15) * 2;      // 0..30
    int j0 = (t & 7) * 4;              // 0..28
    int ia = i0 >> 1;
    int jb = j0 >> 1;

    const float2* Sb = S + (size_t)f * BS * KDIM + kc * 512;
    const float2* Gb = G + (size_t)f * BS * KDIM + kc * 512;
    const float4* Sg4 = (const float4*)(Sb + (size_t)li * KDIM);
    const float4* Gg4 = (const float4*)(Gb + (size_t)li * KDIM);

    float cr[2][4], ci[2][4];
#pragma unroll
    for (int di = 0; di < 2; di++)
#pragma unroll
        for (int dj = 0; dj < 4; dj++) { cr[di][dj] = 0.f; ci[di][dj] = 0.f; }

    const float4* sS4 = (const float4*)sS;
    const float4* sG4 = (const float4*)sG;

    for (int kt = 0; kt < 16; kt++) {          // 16 staged tiles of 32 k
        __syncthreads();
#pragma unroll
        for (int u = 0; u < 2; u++) {
            int k4 = ls + u * 8;               // float4 index 0..15 -> complex k 0..31
            float4 s = Sg4[kt * 16 + k4];
            float4 g = Gg4[kt * 16 + k4];
            sS[(2 * k4)     * 34 + li] = make_float2(s.x, s.y);
            sS[(2 * k4 + 1) * 34 + li] = make_float2(s.z, s.w);
            sG[(2 * k4)     * 34 + li] = make_float2(g.x, g.y);
            sG[(2 * k4 + 1) * 34 + li] = make_float2(g.z, g.w);
        }
        __syncthreads();
#pragma unroll
        for (int kk = 0; kk < 16; kk++) {
            int k = ksub * 16 + kk;
            float4 a  = sS4[k * 17 + ia];          // complexes i0, i0+1
            float4 b0 = sG4[k * 17 + jb];          // complexes j0, j0+1
            float4 b1 = sG4[k * 17 + jb + 1];      // complexes j0+2, j0+3
            // a.xy * conj(b)
            cr[0][0] += a.x * b0.x + a.y * b0.y;  ci[0][0] += a.y * b0.x - a.x * b0.y;
            cr[0][1] += a.x * b0.z + a.y * b0.w;  ci[0][1] += a.y * b0.z - a.x * b0.w;
            cr[0][2] += a.x * b1.x + a.y * b1.y;  ci[0][2] += a.y * b1.x - a.x * b1.y;
            cr[0][3] += a.x * b1.z + a.y * b1.w;  ci[0][3] += a.y * b1.z - a.x * b1.w;
            // a.zw * conj(b)
            cr[1][0] += a.z * b0.x + a.w * b0.y;  ci[1][0] += a.w * b0.x - a.z * b0.y;
            cr[1][1] += a.z * b0.z + a.w * b0.w;  ci[1][1] += a.w * b0.z - a.z * b0.w;
            cr[1][2] += a.z * b1.x + a.w * b1.y;  ci[1][2] += a.w * b1.x - a.z * b1.y;
            cr[1][3] += a.z * b1.z + a.w * b1.w;  ci[1][3] += a.w * b1.z - a.z * b1.w;
        }
    }
    int kc2 = kc * 2 + ksub;
    float2* outp = Cp + ((size_t)kc2 * NF + f) * BS * BS;
#pragma unroll
    for (int di = 0; di < 2; di++)
#pragma unroll
        for (int dj = 0; dj < 4; dj++)
            outp[(i0 + di) * 32 + (j0 + dj)] = make_float2(cr[di][dj], ci[di][dj]);
}

// -------- fused inverse transform + norm + first-max argmax + distance --------
__global__ void k_inv(float* __restrict__ out_dist, float* __restrict__ out_orien_f) {
    __shared__ float2 CH[NF], CW[NF];
    __shared__ float valsH[64], valsW[64];
    __shared__ float nred[2];
    int i = blockIdx.x >> 5, j = blockIdx.x & 31;
    int s = threadIdx.x;

    float nv = g_normp[i * 64 + s];
#pragma unroll
    for (int o = 16; o > 0; o >>= 1) nv += __shfl_down_sync(0xffffffffu, nv, o);
    if ((s & 31) == 0) nred[s >> 5] = nv;

    if (s < NF) {
        float xr = 0, xi = 0, yr = 0, yi = 0;
#pragma unroll
        for (int kc = 0; kc < NKC2; kc++) {
            float2 a = g_CpH[((kc * NF + s) * BS + i) * BS + j];
            float2 b = g_CpW[((kc * NF + s) * BS + i) * BS + j];
            xr += a.x; xi += a.y; yr += b.x; yi += b.y;
        }
        CH[s] = make_float2(xr, xi);
        CW[s] = make_float2(yr, yi);
    }
    __syncthreads();

    float sgn = (s & 1) ? -1.f : 1.f;
    float accH = CH[0].x + sgn * CH[32].x;
    float accW = CW[0].x + sgn * CW[32].x;
#pragma unroll
    for (int f = 1; f < 32; f++) {
        float2 t = g_tw[f * 64 + s];
        accH += 2.f * (CH[f].x * t.x - CH[f].y * t.y);
        accW += 2.f * (CW[f].x * t.x - CW[f].y * t.y);
    }
    valsH[s] = accH;
    valsW[s] = accW;
    __syncthreads();

    if (s == 0) {
        float best = valsH[0]; int bi = 0;
        for (int t = 1; t < 64; t++)
            if (valsH[t] > best) { best = valsH[t]; bi = t; }   // first max
        out_orien_f[i * 32 + j] = (float)bi;
        float nrm = sqrtf(nred[0] + nred[1] + 1e-8f);
        float q = valsW[bi] * (1.f / 64.f);
        float dot = q / nrm;
        out_dist[j * 32 + i] = 2.f - 2.f * dot;
    }
}

extern "C" void kernel_launch(void* const* d_in, const int* in_sizes, int n_in,
                              void* d_out, int out_size) {
    (void)in_sizes; (void)n_in; (void)out_size;
    const float* sat = (const float*)d_in[0];
    const float* grd = (const float*)d_in[1];
    float* out = (float*)d_out;

    k_init<<<9, 256>>>();

    k_dft3<<<4096, 256>>>(sat, grd, out);

    k_fgemm2<<<2 * NF * NKC, 256>>>();

    float* out_dist  = out + (size_t)2 * SATN;
    float* out_orien = out + (size_t)2 * SATN + 1024;
    k_inv<<<1024, 64>>>(out_dist, out_orien);
}

// round 10
// speedup vs baseline: 1.7521x; 1.1380x over previous
#include <cuda_runtime.h>
#include <math.h>

#define BS 32
#define NF 33
#define KDIM 4096
#define SATN (32*64*64*64)
#define NKC 8            // k-chunk blocks per freq in fgemm
#define NKC2 32          // Cp partial slots (NKC * 4 k-subsets)

// -------- device scratch --------
__device__ float2 g_Sh[(size_t)NF * BS * KDIM];
__device__ float2 g_Gh[(size_t)NF * BS * KDIM];
__device__ float2 g_Sw[(size_t)NF * BS * KDIM];
__device__ float2 g_Gw[(size_t)NF * BS * KDIM];
__device__ float2 g_CpH[NKC2 * NF * BS * BS];
__device__ float2 g_CpW[NKC2 * NF * BS * BS];
__device__ float  g_normp[2048];

// -------- DFT helpers (R9-proven) --------
__device__ __forceinline__ void dft_build(
    const float* slab, float* se, float* so, int axisH, int cc, int col, int m)
{
#pragma unroll
    for (int nn = 0; nn < 8; nn++) {
        int n = m + 4 * nn;
        float a, bb;
        if (axisH) {
            a  = slab[n * 65 + cc];
            bb = n ? slab[(64 - n) * 65 + cc] : 0.f;
        } else {
            a  = slab[cc * 65 + n];
            bb = n ? slab[cc * 65 + (64 - n)] : 0.f;
        }
        se[n * 65 + col] = a + bb;
        so[n * 65 + col] = a - bb;
    }
    if (m == 0)
        se[32 * 65 + col] = axisH ? slab[32 * 65 + cc] : slab[cc * 65 + 32];
}

__device__ __forceinline__ void dft_compute(
    const float* se, const float* so, const float2* stw,
    float2* __restrict__ dst, int i, size_t off, int col, int m)
{
    float e0  = se[col];
    float e32 = se[32 * 65 + col];
    float sgn = (m & 1) ? -1.f : 1.f;
    float base = fmaf(sgn, e32, e0);

    float ar1[4], ai1[4], ar2[4], ai2[4];
#pragma unroll
    for (int u = 0; u < 4; u++) { ar1[u] = base; ar2[u] = base; ai1[u] = 0.f; ai2[u] = 0.f; }

#pragma unroll
    for (int n = 1; n < 32; n++) {
        float en = se[n * 65 + col];
        float on = so[n * 65 + col];
#pragma unroll
        for (int u = 0; u < 4; u++) {
            float2 w = stw[(m + 4 * u) * 64 + n];
            ar1[u] = fmaf(en, w.x, ar1[u]);
            ai1[u] = fmaf(on, w.y, ai1[u]);
            float c2, s2;                      // twiddle(f1+16, n) = (-i)^n rotation, exact
            if ((n & 3) == 0)      { c2 =  w.x; s2 =  w.y; }
            else if ((n & 3) == 1) { c2 = -w.y; s2 =  w.x; }
            else if ((n & 3) == 2) { c2 = -w.x; s2 = -w.y; }
            else                   { c2 =  w.y; s2 = -w.x; }
            ar2[u] = fmaf(en, c2, ar2[u]);
            ai2[u] = fmaf(on, s2, ai2[u]);
        }
    }
#pragma unroll
    for (int u = 0; u < 4; u++) {
        int f1 = m + 4 * u;
        dst[((size_t)f1 * BS + i) * KDIM + off]        = make_float2(ar1[u], -ai1[u]);
        dst[((size_t)(f1 + 16) * BS + i) * KDIM + off] = make_float2(ar2[u], -ai2[u]);
    }
    if (m == 0) {                              // f = 32: cos = (-1)^n, sin = 0
        float ar = e0 + e32;
        float sg = -1.f;
#pragma unroll
        for (int n = 1; n < 32; n++) {
            ar = fmaf(se[n * 65 + col], sg, ar);
            sg = -sg;
        }
        dst[((size_t)32 * BS + i) * KDIM + off] = make_float2(ar, 0.f);
    }
}

// -------- merged DFT: sat+grd, H+W axes, passthrough copy, norm, inline twiddles --------
__global__ void __launch_bounds__(256, 4)
k_dft3(const float* __restrict__ sat, const float* __restrict__ grd,
       float* __restrict__ out)
{
    __shared__ float slab[64 * 65];
    __shared__ __align__(16) float2 stw[16 * 64];
    __shared__ float se[33 * 65];
    __shared__ float so[32 * 65];
    __shared__ float red[8];

    int b = blockIdx.x;
    int tid = threadIdx.x;
    int is_grd = (b >= 2048);
    int b2 = is_grd ? (b - 2048) : b;
    const float* p = (is_grd ? grd : sat) + (size_t)b2 * 4096;
    float* op = out + (is_grd ? (size_t)SATN : 0) + (size_t)b2 * 4096;

    float nacc = 0.f;
#pragma unroll
    for (int t = 0; t < 16; t++) {
        int idx = tid + t * 256;
        float v = p[idx];
        slab[(idx >> 6) * 65 + (idx & 63)] = v;
        op[idx] = v;
        nacc = fmaf(v, v, nacc);
    }
    // inline twiddles: identical values to the old k_init table
#pragma unroll
    for (int t = tid; t < 16 * 64; t += 256) {
        int f = t >> 6, n = t & 63;
        float x = (float)((f * n) & 63) / 32.0f;
        float sn, cs;
        sincospif(x, &sn, &cs);
        stw[t] = make_float2(cs, sn);
    }

    if (!is_grd) {
#pragma unroll
        for (int o = 16; o > 0; o >>= 1)
            nacc += __shfl_down_sync(0xffffffffu, nacc, o);
        if ((tid & 31) == 0) red[tid >> 5] = nacc;
    }
    __syncthreads();
    if (!is_grd && tid == 0) {
        float s = 0.f;
#pragma unroll
        for (int w = 0; w < 8; w++) s += red[w];
        g_normp[b2] = s;
    }

    int col = tid & 63;
    int m   = tid >> 6;
    int i = b2 >> 6, c = b2 & 63;
    size_t off = (size_t)c * 64 + col;

    {
        int cc = is_grd ? (63 - col) : col;
        dft_build(slab, se, so, 1, cc, col, m);
        __syncthreads();
        dft_compute(se, so, stw, is_grd ? g_Gh : g_Sh, i, off, col, m);
    }
    __syncthreads();
    {
        dft_build(slab, se, so, 0, col, col, m);
        __syncthreads();
        dft_compute(se, so, stw, is_grd ? g_Gw : g_Sw, i, off, col, m);
    }
}

// -------- per-frequency complex GEMM, 3-mult (Karatsuba) MACs, 4x4 tiles --------
// C[f][i][j] = sum_k S[f][i][k] * conj(G[f][j][k]).
// Per MAC: K1 += br*(ar+ai); K2 += ar*(-bi-br); K3 += ai*(br-bi);
// re = K1-K3, im = K1+K2 (exact identity). 48 FFMA + 6 LDS.128 per k per thread.
// SoA smem, row stride 36 floats (16B-aligned rows, spread staging banks).
#define FST 36
__global__ void __launch_bounds__(256, 2) k_fgemm3() {
    __shared__ __align__(16) float sSr[32 * FST];
    __shared__ __align__(16) float sSi[32 * FST];
    __shared__ __align__(16) float sSp[32 * FST];
    __shared__ __align__(16) float sG1[32 * FST];
    __shared__ __align__(16) float sG2[32 * FST];
    __shared__ __align__(16) float sG3[32 * FST];

    int bid = blockIdx.x;
    int sel = (bid >= NF * NKC);
    if (sel) bid -= NF * NKC;
    int f  = bid >> 3;
    int kc = bid & 7;

    const float2* S = sel ? g_Sw : g_Sh;
    const float2* G = sel ? g_Gw : g_Gh;
    float2* Cp      = sel ? g_CpW : g_CpH;

    int tid = threadIdx.x;
    int li = tid >> 3;                 // staging row 0..31
    int ls = tid & 7;                  // staging float4 k-index base
    int t    = tid & 63;               // tile-thread
    int ksub = tid >> 6;               // 0..3 -> k-subrange within staged tile
    int i0 = (t >> 3) * 4;             // 0,4,...,28
    int j0 = (t & 7) * 4;              // 0,4,...,28

    const float2* Sb = S + (size_t)f * BS * KDIM + kc * 512;
    const float2* Gb = G + (size_t)f * BS * KDIM + kc * 512;
    const float4* Sg4 = (const float4*)(Sb + (size_t)li * KDIM);
    const float4* Gg4 = (const float4*)(Gb + (size_t)li * KDIM);

    float K1[4][4], K2[4][4], K3[4][4];
#pragma unroll
    for (int di = 0; di < 4; di++)
#pragma unroll
        for (int dj = 0; dj < 4; dj++) { K1[di][dj] = 0.f; K2[di][dj] = 0.f; K3[di][dj] = 0.f; }

    for (int kt = 0; kt < 16; kt++) {          // 16 staged tiles of 32 k
        __syncthreads();
#pragma unroll
        for (int u = 0; u < 2; u++) {
            int k4 = ls + u * 8;               // float4 index -> complex k 2k4, 2k4+1 (row li)
            float4 s = Sg4[kt * 16 + k4];
            float4 g = Gg4[kt * 16 + k4];
            int r0 = (2 * k4) * FST + li, r1 = (2 * k4 + 1) * FST + li;
            sSr[r0] = s.x;  sSi[r0] = s.y;  sSp[r0] = s.x + s.y;
            sSr[r1] = s.z;  sSi[r1] = s.w;  sSp[r1] = s.z + s.w;
            sG1[r0] = g.x;  sG2[r0] = -g.y - g.x;  sG3[r0] = g.x - g.y;
            sG1[r1] = g.z;  sG2[r1] = -g.w - g.z;  sG3[r1] = g.z - g.w;
        }
        __syncthreads();
#pragma unroll
        for (int kk = 0; kk < 8; kk++) {
            int k = ksub * 8 + kk;
            float4 var = *(const float4*)&sSr[k * FST + i0];
            float4 vai = *(const float4*)&sSi[k * FST + i0];
            float4 vap = *(const float4*)&sSp[k * FST + i0];
            float4 vg1 = *(const float4*)&sG1[k * FST + j0];
            float4 vg2 = *(const float4*)&sG2[k * FST + j0];
            float4 vg3 = *(const float4*)&sG3[k * FST + j0];
            const float* par = (const float*)&var;
            const float* pai = (const float*)&vai;
            const float* pap = (const float*)&vap;
            const float* pg1 = (const float*)&vg1;
            const float* pg2 = (const float*)&vg2;
            const float* pg3 = (const float*)&vg3;
#pragma unroll
            for (int di = 0; di < 4; di++) {
#pragma unroll
                for (int dj = 0; dj < 4; dj++) {
                    K1[di][dj] = fmaf(pg1[dj], pap[di], K1[di][dj]);
                    K2[di][dj] = fmaf(pg2[dj], par[di], K2[di][dj]);
                    K3[di][dj] = fmaf(pg3[dj], pai[di], K3[di][dj]);
                }
            }
        }
    }
    int kc2 = kc * 4 + ksub;
    float2* outp = Cp + ((size_t)kc2 * NF + f) * BS * BS;
#pragma unroll
    for (int di = 0; di < 4; di++)
#pragma unroll
        for (int dj = 0; dj < 4; dj++)
            outp[(i0 + di) * 32 + (j0 + dj)] =
                make_float2(K1[di][dj] - K3[di][dj], K1[di][dj] + K2[di][dj]);
}

// -------- fused inverse transform + norm + first-max argmax + distance --------
// grid = 256 blocks x 256 threads; each block handles 4 (i,j) pairs (64 threads each).
__global__ void k_inv(float* __restrict__ out_dist, float* __restrict__ out_orien_f) {
    __shared__ float2 CH[4][NF], CW[4][NF];
    __shared__ float valsH[4][64], valsW[4][64];
    __shared__ float nred[4][2];
    int tid = threadIdx.x;
    int p = tid >> 6;                       // pair within block
    int s = tid & 63;                       // shift index
    int pair = blockIdx.x * 4 + p;
    int i = pair >> 5, j = pair & 31;

    // norm[i] partial reduction (64 threads = 2 whole warps per pair)
    float nv = g_normp[i * 64 + s];
#pragma unroll
    for (int o = 16; o > 0; o >>= 1) nv += __shfl_down_sync(0xffffffffu, nv, o);
    if ((s & 31) == 0) nred[p][s >> 5] = nv;

    if (s < NF) {
        float xr = 0, xi = 0, yr = 0, yi = 0;
#pragma unroll
        for (int kc = 0; kc < NKC2; kc++) {
            float2 a = g_CpH[((kc * NF + s) * BS + i) * BS + j];
            float2 b = g_CpW[((kc * NF + s) * BS + i) * BS + j];
            xr += a.x; xi += a.y; yr += b.x; yi += b.y;
        }
        CH[p][s] = make_float2(xr, xi);
        CW[p][s] = make_float2(yr, yi);
    }
    __syncthreads();

    float sgn = (s & 1) ? -1.f : 1.f;
    float accH = CH[p][0].x + sgn * CH[p][32].x;
    float accW = CW[p][0].x + sgn * CW[p][32].x;
#pragma unroll
    for (int f = 1; f < 32; f++) {
        float x = (float)((f * s) & 63) / 32.0f;   // same args as old table -> same values
        float sn, cs;
        sincospif(x, &sn, &cs);
        accH += 2.f * (CH[p][f].x * cs - CH[p][f].y * sn);
        accW += 2.f * (CW[p][f].x * cs - CW[p][f].y * sn);
    }
    valsH[p][s] = accH;
    valsW[p][s] = accW;
    __syncthreads();

    if (s == 0) {
        float best = valsH[p][0]; int bi = 0;
        for (int t = 1; t < 64; t++)
            if (valsH[p][t] > best) { best = valsH[p][t]; bi = t; }   // first max
        out_orien_f[i * 32 + j] = (float)bi;
        float nrm = sqrtf(nred[p][0] + nred[p][1] + 1e-8f);
        float q = valsW[p][bi] * (1.f / 64.f);
        float dot = q / nrm;
        out_dist[j * 32 + i] = 2.f - 2.f * dot;
    }
}

extern "C" void kernel_launch(void* const* d_in, const int* in_sizes, int n_in,
                              void* d_out, int out_size) {
    (void)in_sizes; (void)n_in; (void)out_size;
    const float* sat = (const float*)d_in[0];
    const float* grd = (const float*)d_in[1];
    float* out = (float*)d_out;

    k_dft3<<<4096, 256>>>(sat, grd, out);

    k_fgemm3<<<2 * NF * NKC, 256>>>();

    float* out_dist  = out + (size_t)2 * SATN;
    float* out_orien = out + (size_t)2 * SATN + 1024;
    k_inv<<<256, 256>>>(out_dist, out_orien);
}